// round 1
// baseline (speedup 1.0000x reference)
#include <cuda_runtime.h>
#include <cstdint>

#define EMB 64
#define NMAX 300000

// Scratch (allocation-free rule: __device__ globals)
__device__ int   g_deg [NMAX];
__device__ float g_dinv[NMAX];
__device__ float g_A[(size_t)NMAX * EMB];   // ping
__device__ float g_B[(size_t)NMAX * EMB];   // pong

// ---------------------------------------------------------------------------
__global__ void k_zero_deg(int n) {
    int i = blockIdx.x * blockDim.x + threadIdx.x;
    if (i < n) g_deg[i] = 0;
}

__global__ void k_count(const int* __restrict__ row, int E) {
    int i = blockIdx.x * blockDim.x + threadIdx.x;
    if (i < E) atomicAdd(&g_deg[row[i]], 1);
}

__global__ void k_dinv(int n) {
    int i = blockIdx.x * blockDim.x + threadIdx.x;
    if (i < n) g_dinv[i] = rsqrtf((float)(g_deg[i] + 1));  // +1 self loop
}

// Build x0 into A, zero B, and seed acc (= d_out) with x0.
// One thread per float4 chunk: N*16 chunks.
__global__ void k_init(const float* __restrict__ uemb,
                       const float* __restrict__ iemb,
                       float* __restrict__ acc,
                       int U, int N) {
    int i = blockIdx.x * blockDim.x + threadIdx.x;       // chunk id
    int total = N * (EMB / 4);
    if (i >= total) return;
    int node  = i >> 4;
    int chunk = i & 15;
    const float4* src = (node < U)
        ? (const float4*)(uemb + (size_t)node * EMB)
        : (const float4*)(iemb + (size_t)(node - U) * EMB);
    float4 v = src[chunk];
    ((float4*)g_A)[i]   = v;
    ((float4*)g_B)[i]   = make_float4(0.f, 0.f, 0.f, 0.f);
    ((float4*)acc)[i]   = v;
}

// One edge handled by 16 consecutive threads; each thread moves a float4.
__device__ __forceinline__ void red_add_v4(float* p, float4 v) {
    asm volatile("red.global.add.v4.f32 [%0], {%1,%2,%3,%4};"
                 :: "l"(p), "f"(v.x), "f"(v.y), "f"(v.z), "f"(v.w)
                 : "memory");
}

__global__ void k_scatter(const int* __restrict__ row,
                          const int* __restrict__ col,
                          const float* __restrict__ x,
                          float* __restrict__ y,
                          int E) {
    long long t = (long long)blockIdx.x * blockDim.x + threadIdx.x;
    int e = (int)(t >> 4);
    if (e >= E) return;
    int c  = (int)(t & 15);
    int r  = __ldg(row + e);
    int cl = __ldg(col + e);
    float w = __ldg(&g_dinv[r]) * __ldg(&g_dinv[cl]);
    float4 v = __ldg((const float4*)(x + (size_t)cl * EMB) + c);
    v.x *= w; v.y *= w; v.z *= w; v.w *= w;
    red_add_v4(y + (size_t)r * EMB + c * 4, v);
}

// x_new = y + dinv^2 * x ; acc += x_new ; y <- x_new (in place) ; x <- 0
__global__ void k_finalize(const float* __restrict__ xin,   // = A or B
                           float* __restrict__ yio,         // the other one
                           float* __restrict__ acc,
                           int N) {
    int i = blockIdx.x * blockDim.x + threadIdx.x;
    int total = N * (EMB / 4);
    if (i >= total) return;
    int node = i >> 4;
    float d  = g_dinv[node];
    float sw = d * d;
    float4 xv = ((const float4*)xin)[i];
    float4 yv = ((float4*)yio)[i];
    float4 xn = make_float4(yv.x + sw * xv.x, yv.y + sw * xv.y,
                            yv.z + sw * xv.z, yv.w + sw * xv.w);
    ((float4*)yio)[i] = xn;                       // becomes next-layer x
    float4 a = ((float4*)acc)[i];
    a.x += xn.x; a.y += xn.y; a.z += xn.z; a.w += xn.w;
    ((float4*)acc)[i] = a;
    ((float4*)const_cast<float*>(xin))[i] = make_float4(0.f, 0.f, 0.f, 0.f); // next-layer y
}

// ---------------------------------------------------------------------------
extern "C" void kernel_launch(void* const* d_in, const int* in_sizes, int n_in,
                              void* d_out, int out_size) {
    const int* edge = (const int*)d_in[0];
    const float* uemb = (const float*)d_in[1];
    const float* iemb = (const float*)d_in[2];

    int E = in_sizes[0] / 2;
    int U = in_sizes[1] / EMB;
    int I = in_sizes[2] / EMB;
    int N = U + I;

    const int* row = edge;
    const int* col = edge + E;

    float* acc = (float*)d_out;

    float* dA; cudaGetSymbolAddress((void**)&dA, g_A);
    float* dB; cudaGetSymbolAddress((void**)&dB, g_B);

    const int TB = 256;

    k_zero_deg<<<(N + TB - 1) / TB, TB>>>(N);
    k_count   <<<(E + TB - 1) / TB, TB>>>(row, E);
    k_dinv    <<<(N + TB - 1) / TB, TB>>>(N);

    int chunks = N * (EMB / 4);
    k_init<<<(chunks + TB - 1) / TB, TB>>>(uemb, iemb, acc, U, N);

    long long sthreads = (long long)E * 16;
    int sblocks = (int)((sthreads + TB - 1) / TB);

    float* x = dA;
    float* y = dB;
    for (int l = 0; l < 3; l++) {
        k_scatter <<<sblocks, TB>>>(row, col, x, y, E);
        k_finalize<<<(chunks + TB - 1) / TB, TB>>>(x, y, acc, N);
        float* t = x; x = y; y = t;   // y now holds x_{l+1}; old x zeroed
    }
}

// round 2
// speedup vs baseline: 2.2481x; 2.2481x over previous
#include <cuda_runtime.h>
#include <cstdint>

#define EMB   64
#define NMAX  300000
#define EMAX  4200000
#define TB    256

// ---------------- scratch (__device__ globals; allocation-free rule) --------
__device__ int   g_deg  [NMAX];
__device__ float g_dinv [NMAX];
__device__ int   g_loc  [NMAX];     // within-block exclusive prefix
__device__ int   g_bsum [2048];
__device__ int   g_bbase[2048];
__device__ int   g_off  [NMAX];     // CSR row start
__device__ int   g_cur  [NMAX];     // fill cursor
__device__ int2  g_adj  [EMAX];     // {col, bits(dinv[col])}
__device__ float g_A[(size_t)NMAX * EMB];
__device__ float g_B[(size_t)NMAX * EMB];

// ---------------------------------------------------------------------------
__global__ void k_zero_deg(int n) {
    int i = blockIdx.x * blockDim.x + threadIdx.x;
    if (i < n) g_deg[i] = 0;
}

__global__ void k_count(const int* __restrict__ row, int E) {
    int i = blockIdx.x * blockDim.x + threadIdx.x;
    if (i < E) atomicAdd(&g_deg[row[i]], 1);
}

// per-block inclusive scan of deg -> local exclusive prefix + block sums
__global__ void k_scan_local(int n) {
    __shared__ int sh[TB];
    int i = blockIdx.x * TB + threadIdx.x;
    int v = (i < n) ? g_deg[i] : 0;
    sh[threadIdx.x] = v; __syncthreads();
    #pragma unroll
    for (int ofs = 1; ofs < TB; ofs <<= 1) {
        int t = (threadIdx.x >= ofs) ? sh[threadIdx.x - ofs] : 0;
        __syncthreads();
        sh[threadIdx.x] += t;
        __syncthreads();
    }
    if (i < n) g_loc[i] = sh[threadIdx.x] - v;
    if (threadIdx.x == TB - 1) g_bsum[blockIdx.x] = sh[TB - 1];
}

// single-block scan of up to 2048 block sums (1024 threads, 2 elems each)
__global__ void k_scan_bsum(int nb) {
    __shared__ int sh[1024];
    int tid = threadIdx.x;
    int c0 = tid * 2, c1 = tid * 2 + 1;
    int a = (c0 < nb) ? g_bsum[c0] : 0;
    int b = (c1 < nb) ? g_bsum[c1] : 0;
    int tot = a + b;
    sh[tid] = tot; __syncthreads();
    #pragma unroll
    for (int ofs = 1; ofs < 1024; ofs <<= 1) {
        int t = (tid >= ofs) ? sh[tid - ofs] : 0;
        __syncthreads();
        sh[tid] += t;
        __syncthreads();
    }
    int base = sh[tid] - tot;
    if (c0 < nb) g_bbase[c0] = base;
    if (c1 < nb) g_bbase[c1] = base + a;
}

// offsets = local + block base; also dinv and fill cursors
__global__ void k_scan_add(int n) {
    int i = blockIdx.x * TB + threadIdx.x;
    if (i >= n) return;
    int o = g_loc[i] + g_bbase[blockIdx.x];
    g_off[i] = o;
    g_cur[i] = o;
    g_dinv[i] = rsqrtf((float)(g_deg[i] + 1));   // +1 self loop
}

__global__ void k_fill(const int* __restrict__ row, const int* __restrict__ col, int E) {
    int e = blockIdx.x * blockDim.x + threadIdx.x;
    if (e >= E) return;
    int r = row[e];
    int c = col[e];
    int pos = atomicAdd(&g_cur[r], 1);
    g_adj[pos] = make_int2(c, __float_as_int(g_dinv[c]));
}

// ---------------------------------------------------------------------------
__device__ __forceinline__ float4 ld_emb(const float* __restrict__ ue,
                                         const float* __restrict__ ie,
                                         int U, int node, int c) {
    const float4* p = (node < U)
        ? (const float4*)ue + (size_t)node * 16
        : (const float4*)ie + (size_t)(node - U) * 16;
    return __ldg(p + c);
}

// Fused layer: 16 threads per node, each owns one float4 chunk.
// x_new = sum_{nbr} w * x[col] + d^2 * x[node]; acc (+)= x_new.
template<bool FIRST, bool LAST>
__global__ void k_layer(const float* __restrict__ x,
                        const float* __restrict__ ue,
                        const float* __restrict__ ie,
                        int U,
                        float* __restrict__ xn,
                        float* __restrict__ acc,
                        int N) {
    int t = blockIdx.x * blockDim.x + threadIdx.x;
    int node = t >> 4;
    if (node >= N) return;
    int c = t & 15;

    float d = __ldg(&g_dinv[node]);
    int beg = __ldg(&g_off[node]);
    int end = beg + __ldg(&g_deg[node]);

    float4 xs = FIRST ? ld_emb(ue, ie, U, node, c)
                      : __ldg((const float4*)x + (size_t)node * 16 + c);
    float sw = d * d;
    float4 s = make_float4(sw * xs.x, sw * xs.y, sw * xs.z, sw * xs.w);

    // software-pipelined neighbor loop
    int e = beg;
    int2 nxt = (e < end) ? __ldg(&g_adj[e]) : make_int2(0, 0);
    while (e < end) {
        int2 cur = nxt;
        ++e;
        if (e < end) nxt = __ldg(&g_adj[e]);
        float w = d * __int_as_float(cur.y);
        float4 v = FIRST ? ld_emb(ue, ie, U, cur.x, c)
                         : __ldg((const float4*)x + (size_t)cur.x * 16 + c);
        s.x += w * v.x; s.y += w * v.y; s.z += w * v.z; s.w += w * v.w;
    }

    size_t idx = (size_t)node * 16 + c;
    if (!LAST) ((float4*)xn)[idx] = s;

    float4 a;
    if (FIRST) {
        a = xs;                           // acc starts at x0 (layer-0 term)
    } else {
        a = ((const float4*)acc)[idx];
    }
    a.x += s.x; a.y += s.y; a.z += s.z; a.w += s.w;
    ((float4*)acc)[idx] = a;
}

// ---------------------------------------------------------------------------
extern "C" void kernel_launch(void* const* d_in, const int* in_sizes, int n_in,
                              void* d_out, int out_size) {
    const int*   edge = (const int*)d_in[0];
    const float* uemb = (const float*)d_in[1];
    const float* iemb = (const float*)d_in[2];

    int E = in_sizes[0] / 2;
    int U = in_sizes[1] / EMB;
    int I = in_sizes[2] / EMB;
    int N = U + I;

    const int* row = edge;
    const int* col = edge + E;
    float* acc = (float*)d_out;

    float* dA; cudaGetSymbolAddress((void**)&dA, g_A);
    float* dB; cudaGetSymbolAddress((void**)&dB, g_B);

    int NB = (N + TB - 1) / TB;          // <= 1172 blocks, fits 2048 scan
    int EB = (E + TB - 1) / TB;

    k_zero_deg  <<<NB, TB>>>(N);
    k_count     <<<EB, TB>>>(row, E);
    k_scan_local<<<NB, TB>>>(N);
    k_scan_bsum <<<1, 1024>>>(NB);
    k_scan_add  <<<NB, TB>>>(N);
    k_fill      <<<EB, TB>>>(row, col, E);

    int lblocks = (N * 16 + TB - 1) / TB;
    k_layer<true,  false><<<lblocks, TB>>>(nullptr, uemb, iemb, U, dA, acc, N);
    k_layer<false, false><<<lblocks, TB>>>(dA,      uemb, iemb, U, dB, acc, N);
    k_layer<false, true ><<<lblocks, TB>>>(dB,      uemb, iemb, U, nullptr, acc, N);
}

// round 3
// speedup vs baseline: 2.3443x; 1.0428x over previous
#include <cuda_runtime.h>
#include <cstdint>

#define EMB   64
#define NMAX  300000
#define EMAX  4200000
#define TB    256

// ---------------- scratch (__device__ globals; allocation-free rule) --------
__device__ int   g_deg  [NMAX];
__device__ float g_dinv [NMAX];
__device__ int   g_loc  [NMAX];     // within-block exclusive prefix
__device__ int   g_bsum [2048];
__device__ int   g_bbase[2048];
__device__ int2  g_rng  [NMAX];     // {row_start, cursor/row_end}
__device__ int2  g_adj  [EMAX];     // {col, bits(dinv[col])}
__device__ float g_A[(size_t)NMAX * EMB];
__device__ float g_B[(size_t)NMAX * EMB];

// ---------------------------------------------------------------------------
__global__ void k_zero_deg(int n) {
    int i = blockIdx.x * blockDim.x + threadIdx.x;
    if (i < n) g_deg[i] = 0;
}

__global__ void k_count(const int* __restrict__ row, int E) {
    int i = blockIdx.x * blockDim.x + threadIdx.x;
    if (i < E) atomicAdd(&g_deg[row[i]], 1);
}

// per-block inclusive scan of deg -> local exclusive prefix + block sums
__global__ void k_scan_local(int n) {
    __shared__ int sh[TB];
    int i = blockIdx.x * TB + threadIdx.x;
    int v = (i < n) ? g_deg[i] : 0;
    sh[threadIdx.x] = v; __syncthreads();
    #pragma unroll
    for (int ofs = 1; ofs < TB; ofs <<= 1) {
        int t = (threadIdx.x >= ofs) ? sh[threadIdx.x - ofs] : 0;
        __syncthreads();
        sh[threadIdx.x] += t;
        __syncthreads();
    }
    if (i < n) g_loc[i] = sh[threadIdx.x] - v;
    if (threadIdx.x == TB - 1) g_bsum[blockIdx.x] = sh[TB - 1];
}

// single-block scan of up to 2048 block sums
__global__ void k_scan_bsum(int nb) {
    __shared__ int sh[1024];
    int tid = threadIdx.x;
    int c0 = tid * 2, c1 = tid * 2 + 1;
    int a = (c0 < nb) ? g_bsum[c0] : 0;
    int b = (c1 < nb) ? g_bsum[c1] : 0;
    int tot = a + b;
    sh[tid] = tot; __syncthreads();
    #pragma unroll
    for (int ofs = 1; ofs < 1024; ofs <<= 1) {
        int t = (tid >= ofs) ? sh[tid - ofs] : 0;
        __syncthreads();
        sh[tid] += t;
        __syncthreads();
    }
    int base = sh[tid] - tot;
    if (c0 < nb) g_bbase[c0] = base;
    if (c1 < nb) g_bbase[c1] = base + a;
}

// offsets = local + block base; dinv; init range {start, cursor=start}
__global__ void k_scan_add(int n) {
    int i = blockIdx.x * TB + threadIdx.x;
    if (i >= n) return;
    int o = g_loc[i] + g_bbase[blockIdx.x];
    g_rng[i] = make_int2(o, o);
    g_dinv[i] = rsqrtf((float)(g_deg[i] + 1));   // +1 self loop
}

__global__ void k_fill(const int* __restrict__ row, const int* __restrict__ col, int E) {
    int e = blockIdx.x * blockDim.x + threadIdx.x;
    if (e >= E) return;
    int r = row[e];
    int c = col[e];
    int pos = atomicAdd(&g_rng[r].y, 1);         // cursor ends at row_end
    g_adj[pos] = make_int2(c, __float_as_int(g_dinv[c]));
}

// ---------------------------------------------------------------------------
__device__ __forceinline__ float4 ld_emb(const float* __restrict__ ue,
                                         const float* __restrict__ ie,
                                         int U, int node, int c) {
    const float4* p = (node < U)
        ? (const float4*)ue + (size_t)node * 16
        : (const float4*)ie + (size_t)(node - U) * 16;
    return __ldg(p + c);
}

// Fused layer: 16 threads per node, each owns one float4 chunk.
// x_new = sum_{nbr} w * x[col] + d^2 * x[node]; acc (+)= x_new.
template<bool FIRST, bool LAST>
__global__ void __launch_bounds__(TB)
k_layer(const float* __restrict__ x,
        const float* __restrict__ ue,
        const float* __restrict__ ie,
        int U,
        float* __restrict__ xn,
        float* __restrict__ acc,
        int N) {
    int t = blockIdx.x * blockDim.x + threadIdx.x;
    int node = t >> 4;
    if (node >= N) return;
    int c = t & 15;

    float d = __ldg(&g_dinv[node]);
    int2 rng = __ldg(&g_rng[node]);
    int e = rng.x, end = rng.y;

    float4 xs = FIRST ? ld_emb(ue, ie, U, node, c)
                      : __ldg((const float4*)x + (size_t)node * 16 + c);
    float sw = d * d;
    float4 s0 = make_float4(sw * xs.x, sw * xs.y, sw * xs.z, sw * xs.w);
    float4 s1 = make_float4(0.f, 0.f, 0.f, 0.f);

    // unrolled-by-2 neighbor loop: 4 independent loads in flight,
    // two accumulator chains
    while (e + 2 <= end) {
        int2 a0 = __ldg(&g_adj[e]);
        int2 a1 = __ldg(&g_adj[e + 1]);
        float4 v0 = FIRST ? ld_emb(ue, ie, U, a0.x, c)
                          : __ldg((const float4*)x + (size_t)a0.x * 16 + c);
        float4 v1 = FIRST ? ld_emb(ue, ie, U, a1.x, c)
                          : __ldg((const float4*)x + (size_t)a1.x * 16 + c);
        float w0 = d * __int_as_float(a0.y);
        float w1 = d * __int_as_float(a1.y);
        s0.x += w0 * v0.x; s0.y += w0 * v0.y; s0.z += w0 * v0.z; s0.w += w0 * v0.w;
        s1.x += w1 * v1.x; s1.y += w1 * v1.y; s1.z += w1 * v1.z; s1.w += w1 * v1.w;
        e += 2;
    }
    if (e < end) {
        int2 a0 = __ldg(&g_adj[e]);
        float4 v0 = FIRST ? ld_emb(ue, ie, U, a0.x, c)
                          : __ldg((const float4*)x + (size_t)a0.x * 16 + c);
        float w0 = d * __int_as_float(a0.y);
        s0.x += w0 * v0.x; s0.y += w0 * v0.y; s0.z += w0 * v0.z; s0.w += w0 * v0.w;
    }
    float4 s = make_float4(s0.x + s1.x, s0.y + s1.y, s0.z + s1.z, s0.w + s1.w);

    size_t idx = (size_t)node * 16 + c;
    if (!LAST) ((float4*)xn)[idx] = s;

    float4 a;
    if (FIRST) {
        a = xs;                           // acc starts at x0 (layer-0 term)
    } else {
        a = ((const float4*)acc)[idx];
    }
    a.x += s.x; a.y += s.y; a.z += s.z; a.w += s.w;
    ((float4*)acc)[idx] = a;
}

// ---------------------------------------------------------------------------
extern "C" void kernel_launch(void* const* d_in, const int* in_sizes, int n_in,
                              void* d_out, int out_size) {
    const int*   edge = (const int*)d_in[0];
    const float* uemb = (const float*)d_in[1];
    const float* iemb = (const float*)d_in[2];

    int E = in_sizes[0] / 2;
    int U = in_sizes[1] / EMB;
    int I = in_sizes[2] / EMB;
    int N = U + I;

    const int* row = edge;
    const int* col = edge + E;
    float* acc = (float*)d_out;

    float* dA; cudaGetSymbolAddress((void**)&dA, g_A);
    float* dB; cudaGetSymbolAddress((void**)&dB, g_B);

    int NB = (N + TB - 1) / TB;          // <= 1172 blocks, fits 2048 scan
    int EB = (E + TB - 1) / TB;

    k_zero_deg  <<<NB, TB>>>(N);
    k_count     <<<EB, TB>>>(row, E);
    k_scan_local<<<NB, TB>>>(N);
    k_scan_bsum <<<1, 1024>>>(NB);
    k_scan_add  <<<NB, TB>>>(N);
    k_fill      <<<EB, TB>>>(row, col, E);

    int lblocks = (N * 16 + TB - 1) / TB;
    k_layer<true,  false><<<lblocks, TB>>>(nullptr, uemb, iemb, U, dA, acc, N);
    k_layer<false, false><<<lblocks, TB>>>(dA,      uemb, iemb, U, dB, acc, N);
    k_layer<false, true ><<<lblocks, TB>>>(dB,      uemb, iemb, U, nullptr, acc, N);
}

// round 4
// speedup vs baseline: 2.9194x; 1.2453x over previous
#include <cuda_runtime.h>
#include <cuda_fp16.h>
#include <cstdint>

#define EMB   64
#define NMAX  300000
#define EMAX  4200000
#define TB    256

// ---------------- scratch (__device__ globals; allocation-free rule) --------
__device__ int   g_deg  [NMAX];
__device__ float g_dinv [NMAX];
__device__ int   g_loc  [NMAX];
__device__ int   g_bsum [2048];
__device__ int   g_bbase[2048];
__device__ int2  g_rng  [NMAX];               // {row_start, cursor/row_end}
__device__ int   g_adjc [EMAX];               // col index only
__device__ uint2 g_h0[(size_t)NMAX * 16];     // x0 fp16 (4 halves per uint2)
__device__ uint2 g_h1[(size_t)NMAX * 16];     // x1 fp16
__device__ uint2 g_h2[(size_t)NMAX * 16];     // x2 fp16

// ---------------------------------------------------------------------------
__device__ __forceinline__ float4 h4_to_f4(uint2 h) {
    __half2 a = *(__half2*)&h.x;
    __half2 b = *(__half2*)&h.y;
    float2 fa = __half22float2(a), fb = __half22float2(b);
    return make_float4(fa.x, fa.y, fb.x, fb.y);
}
__device__ __forceinline__ uint2 f4_to_h4(float4 v) {
    __half2 a = __floats2half2_rn(v.x, v.y);
    __half2 b = __floats2half2_rn(v.z, v.w);
    uint2 r;
    r.x = *(unsigned*)&a;
    r.y = *(unsigned*)&b;
    return r;
}

// ---------------------------------------------------------------------------
__global__ void k_zero_deg(int n) {
    int i = blockIdx.x * blockDim.x + threadIdx.x;
    if (i < n) g_deg[i] = 0;
}

__global__ void k_count(const int* __restrict__ row, int E) {
    int i = blockIdx.x * blockDim.x + threadIdx.x;
    if (i < E) atomicAdd(&g_deg[row[i]], 1);
}

__global__ void k_scan_local(int n) {
    __shared__ int sh[TB];
    int i = blockIdx.x * TB + threadIdx.x;
    int v = (i < n) ? g_deg[i] : 0;
    sh[threadIdx.x] = v; __syncthreads();
    #pragma unroll
    for (int ofs = 1; ofs < TB; ofs <<= 1) {
        int t = (threadIdx.x >= ofs) ? sh[threadIdx.x - ofs] : 0;
        __syncthreads();
        sh[threadIdx.x] += t;
        __syncthreads();
    }
    if (i < n) g_loc[i] = sh[threadIdx.x] - v;
    if (threadIdx.x == TB - 1) g_bsum[blockIdx.x] = sh[TB - 1];
}

__global__ void k_scan_bsum(int nb) {
    __shared__ int sh[1024];
    int tid = threadIdx.x;
    int c0 = tid * 2, c1 = tid * 2 + 1;
    int a = (c0 < nb) ? g_bsum[c0] : 0;
    int b = (c1 < nb) ? g_bsum[c1] : 0;
    int tot = a + b;
    sh[tid] = tot; __syncthreads();
    #pragma unroll
    for (int ofs = 1; ofs < 1024; ofs <<= 1) {
        int t = (tid >= ofs) ? sh[tid - ofs] : 0;
        __syncthreads();
        sh[tid] += t;
        __syncthreads();
    }
    int base = sh[tid] - tot;
    if (c0 < nb) g_bbase[c0] = base;
    if (c1 < nb) g_bbase[c1] = base + a;
}

__global__ void k_scan_add(int n) {
    int i = blockIdx.x * TB + threadIdx.x;
    if (i >= n) return;
    int o = g_loc[i] + g_bbase[blockIdx.x];
    g_rng[i] = make_int2(o, o);
    g_dinv[i] = rsqrtf((float)(g_deg[i] + 1));   // +1 self loop
}

__global__ void k_fill(const int* __restrict__ row, const int* __restrict__ col, int E) {
    int e = blockIdx.x * blockDim.x + threadIdx.x;
    if (e >= E) return;
    int r = row[e];
    int pos = atomicAdd(&g_rng[r].y, 1);
    g_adjc[pos] = col[e];
}

// emb (fp32) -> x0 (fp16)
__global__ void k_prep(const float* __restrict__ ue,
                       const float* __restrict__ ie,
                       int U, int N) {
    int i = blockIdx.x * blockDim.x + threadIdx.x;   // uint2-chunk id
    int total = N * 16;
    if (i >= total) return;
    int node = i >> 4;
    int c = i & 15;
    const float4* p = (node < U)
        ? (const float4*)ue + (size_t)node * 16
        : (const float4*)ie + (size_t)(node - U) * 16;
    g_h0[i] = f4_to_h4(__ldg(p + c));
}

// ---------------------------------------------------------------------------
// Fused layer: 16 threads per node, thread c owns halves [4c, 4c+4).
// x_new = sum_{nbr} d*dinv[col]*x[col] + d^2*x[node]
// LAST: acc = emb + x1 + x2(self, = xs) + x3(s)
template<bool LAST>
__global__ void __launch_bounds__(TB)
k_layer(const uint2* __restrict__ x,       // fp16 input matrix
        uint2* __restrict__ xn,            // fp16 output (unless LAST)
        const float* __restrict__ ue,
        const float* __restrict__ ie,
        int U,
        float* __restrict__ acc,
        int N) {
    int t = blockIdx.x * blockDim.x + threadIdx.x;
    int node = t >> 4;
    if (node >= N) return;
    int c = t & 15;

    float d = __ldg(&g_dinv[node]);
    int2 rng = __ldg(&g_rng[node]);
    int e = rng.x, end = rng.y;

    size_t idx = (size_t)node * 16 + c;
    float4 xs = h4_to_f4(__ldg(x + idx));
    float sw = d * d;
    float4 s0 = make_float4(sw * xs.x, sw * xs.y, sw * xs.z, sw * xs.w);
    float4 s1 = make_float4(0.f, 0.f, 0.f, 0.f);

    while (e + 2 <= end) {
        int c0 = __ldg(&g_adjc[e]);
        int c1 = __ldg(&g_adjc[e + 1]);
        float4 v0 = h4_to_f4(__ldg(x + (size_t)c0 * 16 + c));
        float4 v1 = h4_to_f4(__ldg(x + (size_t)c1 * 16 + c));
        float w0 = d * __ldg(&g_dinv[c0]);
        float w1 = d * __ldg(&g_dinv[c1]);
        s0.x += w0 * v0.x; s0.y += w0 * v0.y; s0.z += w0 * v0.z; s0.w += w0 * v0.w;
        s1.x += w1 * v1.x; s1.y += w1 * v1.y; s1.z += w1 * v1.z; s1.w += w1 * v1.w;
        e += 2;
    }
    if (e < end) {
        int c0 = __ldg(&g_adjc[e]);
        float4 v0 = h4_to_f4(__ldg(x + (size_t)c0 * 16 + c));
        float w0 = d * __ldg(&g_dinv[c0]);
        s0.x += w0 * v0.x; s0.y += w0 * v0.y; s0.z += w0 * v0.z; s0.w += w0 * v0.w;
    }
    float4 s = make_float4(s0.x + s1.x, s0.y + s1.y, s0.z + s1.z, s0.w + s1.w);

    if (!LAST) {
        xn[idx] = f4_to_h4(s);
    } else {
        // acc = emb(node) + x1 + x2 + x3   (x2 self row already in xs)
        const float4* p = (node < U)
            ? (const float4*)ue + (size_t)node * 16
            : (const float4*)ie + (size_t)(node - U) * 16;
        float4 a  = __ldg(p + c);
        float4 v1 = h4_to_f4(__ldg(&g_h1[idx]));
        a.x += v1.x + xs.x + s.x;
        a.y += v1.y + xs.y + s.y;
        a.z += v1.z + xs.z + s.z;
        a.w += v1.w + xs.w + s.w;
        ((float4*)acc)[idx] = a;
    }
}

// ---------------------------------------------------------------------------
extern "C" void kernel_launch(void* const* d_in, const int* in_sizes, int n_in,
                              void* d_out, int out_size) {
    const int*   edge = (const int*)d_in[0];
    const float* uemb = (const float*)d_in[1];
    const float* iemb = (const float*)d_in[2];

    int E = in_sizes[0] / 2;
    int U = in_sizes[1] / EMB;
    int I = in_sizes[2] / EMB;
    int N = U + I;

    const int* row = edge;
    const int* col = edge + E;
    float* acc = (float*)d_out;

    uint2* h0; cudaGetSymbolAddress((void**)&h0, g_h0);
    uint2* h1; cudaGetSymbolAddress((void**)&h1, g_h1);
    uint2* h2; cudaGetSymbolAddress((void**)&h2, g_h2);

    int NB = (N + TB - 1) / TB;
    int EB = (E + TB - 1) / TB;

    k_zero_deg  <<<NB, TB>>>(N);
    k_count     <<<EB, TB>>>(row, E);
    k_scan_local<<<NB, TB>>>(N);
    k_scan_bsum <<<1, 1024>>>(NB);
    k_scan_add  <<<NB, TB>>>(N);
    k_fill      <<<EB, TB>>>(row, col, E);

    int lblocks = (N * 16 + TB - 1) / TB;
    k_prep<<<lblocks, TB>>>(uemb, iemb, U, N);
    k_layer<false><<<lblocks, TB>>>(h0, h1, uemb, iemb, U, acc, N);
    k_layer<false><<<lblocks, TB>>>(h1, h2, uemb, iemb, U, acc, N);
    k_layer<true ><<<lblocks, TB>>>(h2, nullptr, uemb, iemb, U, acc, N);
}